// round 16
// baseline (speedup 1.0000x reference)
#include <cuda_runtime.h>
#include <cuda_bf16.h>
#include <math.h>
#include <stdint.h>

// Problem constants
#define S_LEN 2048
#define D_DIM 1024
#define H_NUM 16
#define HDIM  64
#define FF_DIM 4096
#define CCH   64
#define NCH   (S_LEN/CCH)
#define EHC   32                 // e-columns per split block

// ---------------- scratch (static device globals; no allocation) ----------
__device__ float g_h   [S_LEN*D_DIM];
__device__ float g_q   [S_LEN*D_DIM];
__device__ float g_k   [S_LEN*D_DIM];
__device__ float g_v   [S_LEN*D_DIM];
__device__ float g_attn[S_LEN*D_DIM];
__device__ float g_x2  [S_LEN*D_DIM];
__device__ float g_h2  [S_LEN*D_DIM];
__device__ float g_ff  [S_LEN*FF_DIM];
__device__ float g_kv  [H_NUM*NCH*HDIM*HDIM];
__device__ float g_kvp [H_NUM*NCH*HDIM*HDIM];
__device__ float g_zc  [H_NUM*NCH*HDIM];
__device__ float g_zp  [H_NUM*NCH*HDIM];

// ---------------- LayerNorm -------------------------------------------------
__global__ void ln_kernel(const float* __restrict__ x,
                          const float* __restrict__ g,
                          const float* __restrict__ b,
                          float* __restrict__ out) {
    int row = blockIdx.x;
    const float* xr = x + (size_t)row * D_DIM;
    float s = 0.f, s2 = 0.f;
    for (int i = threadIdx.x; i < D_DIM; i += 256) {
        float v = xr[i];
        s += v; s2 += v * v;
    }
    __shared__ float sh[64];
    for (int off = 16; off > 0; off >>= 1) {
        s  += __shfl_down_sync(0xffffffffu, s,  off);
        s2 += __shfl_down_sync(0xffffffffu, s2, off);
    }
    int w = threadIdx.x >> 5, l = threadIdx.x & 31;
    if (l == 0) { sh[w] = s; sh[w + 32] = s2; }
    __syncthreads();
    if (threadIdx.x == 0) {
        float ts = 0.f, ts2 = 0.f;
        for (int i = 0; i < 8; i++) { ts += sh[i]; ts2 += sh[i + 32]; }
        float mu = ts / D_DIM;
        sh[0] = mu;
        sh[1] = rsqrtf(ts2 / D_DIM - mu * mu + 1e-5f);
    }
    __syncthreads();
    float mu = sh[0], rstd = sh[1];
    for (int i = threadIdx.x; i < D_DIM; i += 256)
        out[(size_t)row * D_DIM + i] = (xr[i] - mu) * rstd * g[i] + b[i];
}

// ---------------- bf16-split tensor-core GEMM (NT) -------------------------
// C[M,N] = A[M,K] @ B[N,K]^T + epilogue, fp32 in/out.
// Each fp32 = hi_bf16 + lo_bf16; per k16: mma(hi,hi)+mma(hi,lo)+mma(lo,hi).
// Interleaved hi/lo smem layout: row = [hi01, lo01, hi23, lo23, ...] so one
// LDS.64 fetches a fragment's hi+lo words. 2-stage double buffer.
enum { EPI_BIAS = 0, EPI_PHI = 1, EPI_GELU = 2, EPI_RES = 3 };
enum { MODE_ONE = 0, MODE_PAIR = 1 };

__device__ __forceinline__ void mma_bf16(float* c, const unsigned* a, const unsigned* b) {
    asm volatile(
        "mma.sync.aligned.m16n8k16.row.col.f32.bf16.bf16.f32 "
        "{%0,%1,%2,%3}, {%4,%5,%6,%7}, {%8,%9}, {%0,%1,%2,%3};\n"
        : "+f"(c[0]), "+f"(c[1]), "+f"(c[2]), "+f"(c[3])
        : "r"(a[0]), "r"(a[1]), "r"(a[2]), "r"(a[3]), "r"(b[0]), "r"(b[1]));
}

// fp32x4 -> interleaved [hi01, lo01, hi23, lo23]; rn split, bit-identical.
__device__ __forceinline__ uint4 cvt_pack_il(float4 v) {
    uint4 r;
    asm("cvt.rn.bf16x2.f32 %0, %1, %2;" : "=r"(r.x) : "f"(v.y), "f"(v.x));
    asm("cvt.rn.bf16x2.f32 %0, %1, %2;" : "=r"(r.z) : "f"(v.w), "f"(v.z));
    float hx = __uint_as_float(r.x << 16);
    float hy = __uint_as_float(r.x & 0xFFFF0000u);
    float hz = __uint_as_float(r.z << 16);
    float hw = __uint_as_float(r.z & 0xFFFF0000u);
    asm("cvt.rn.bf16x2.f32 %0, %1, %2;" : "=r"(r.y) : "f"(v.y - hy), "f"(v.x - hx));
    asm("cvt.rn.bf16x2.f32 %0, %1, %2;" : "=r"(r.w) : "f"(v.w - hw), "f"(v.z - hz));
    return r;
}

#define LDSW 40                            // words per row (32 data + 8 pad)
#define TILE_WORDS (128 * LDSW)            // per matrix per stage
#define STAGE_WORDS (2 * TILE_WORDS)       // A then B
#define SMEM_GEMM (2 * STAGE_WORDS * 4)    // bytes = 81920

template <int EPI, int MODE>
__global__ __launch_bounds__(256, 1)
void gemm_mma(const float* __restrict__ A,
              const float* __restrict__ B0, const float* __restrict__ B1,
              const float* __restrict__ bias0, const float* __restrict__ bias1,
              const float* __restrict__ res,
              float* __restrict__ C0, float* __restrict__ C1,
              int M, int N, int K) {
    extern __shared__ __align__(16) unsigned SM[];

    const float* B    = B0;
    const float* bias = bias0;
    float*       Cmat = C0;
    if (MODE == MODE_PAIR && blockIdx.z == 1) { B = B1; bias = bias1; Cmat = C1; }

    const int tid  = threadIdx.x;
    const int bm   = blockIdx.y * 128, bn = blockIdx.x * 128;
    const int lane = tid & 31, warp = tid >> 5;
    const int wm   = (warp & 3) * 32;     // 4 warps along M
    const int wn   = (warp >> 2) * 64;    // 2 warps along N
    const int g    = lane >> 2;           // 0..7
    const int tg   = (lane & 3) * 2;      // 0,2,4,6

    const int lrow = tid >> 3;            // 0..31 (loader row)
    const int lcol = (tid & 7) * 4;       // 0..28 (k offset, = word offset)

    float acc[2][8][4];
#pragma unroll
    for (int i = 0; i < 2; i++)
#pragma unroll
        for (int j = 0; j < 8; j++)
#pragma unroll
            for (int e = 0; e < 4; e++) acc[i][j][e] = 0.f;

    const float* Ap = A + (size_t)(bm + lrow) * K + lcol;
    const float* Bp = B + (size_t)(bn + lrow) * K + lcol;

    float4 ar[4], br[4];
#pragma unroll
    for (int i = 0; i < 4; i++) {
        ar[i] = *(const float4*)(Ap + (size_t)(32 * i) * K);
        br[i] = *(const float4*)(Bp + (size_t)(32 * i) * K);
    }

    // convert regs -> stage s (interleaved hi/lo words)
    auto cvt_sts = [&](int s) {
        unsigned* Aw = SM + s * STAGE_WORDS;
        unsigned* Bw = Aw + TILE_WORDS;
#pragma unroll
        for (int i = 0; i < 4; i++) {
            int r = lrow + 32 * i;
            *(uint4*)&Aw[r * LDSW + lcol] = cvt_pack_il(ar[i]);
            *(uint4*)&Bw[r * LDSW + lcol] = cvt_pack_il(br[i]);
        }
    };

    cvt_sts(0);
    __syncthreads();

    const int nb = K / 32;
    for (int t = 0; t < nb; t++) {
        const int s = t & 1;
        if (t + 1 < nb) {
            int kt = (t + 1) * 32;
#pragma unroll
            for (int i = 0; i < 4; i++) {
                ar[i] = *(const float4*)(Ap + kt + (size_t)(32 * i) * K);
                br[i] = *(const float4*)(Bp + kt + (size_t)(32 * i) * K);
            }
        }
        const unsigned* Aw = SM + s * STAGE_WORDS;
        const unsigned* Bw = Aw + TILE_WORDS;
#pragma unroll
        for (int kk = 0; kk < 32; kk += 16) {
            unsigned ah[2][4], al[2][4], bh[8][2], bl[8][2];
#pragma unroll
            for (int mi = 0; mi < 2; mi++) {
                int r0 = wm + mi * 16 + g;
                uint2 p0 = *(const uint2*)&Aw[(r0    ) * LDSW + kk + tg    ];
                uint2 p1 = *(const uint2*)&Aw[(r0 + 8) * LDSW + kk + tg    ];
                uint2 p2 = *(const uint2*)&Aw[(r0    ) * LDSW + kk + tg + 8];
                uint2 p3 = *(const uint2*)&Aw[(r0 + 8) * LDSW + kk + tg + 8];
                ah[mi][0] = p0.x; al[mi][0] = p0.y;
                ah[mi][1] = p1.x; al[mi][1] = p1.y;
                ah[mi][2] = p2.x; al[mi][2] = p2.y;
                ah[mi][3] = p3.x; al[mi][3] = p3.y;
            }
#pragma unroll
            for (int ni = 0; ni < 8; ni++) {
                int c0 = wn + ni * 8 + g;
                uint2 p0 = *(const uint2*)&Bw[c0 * LDSW + kk + tg    ];
                uint2 p1 = *(const uint2*)&Bw[c0 * LDSW + kk + tg + 8];
                bh[ni][0] = p0.x; bl[ni][0] = p0.y;
                bh[ni][1] = p1.x; bl[ni][1] = p1.y;
            }
#pragma unroll
            for (int mi = 0; mi < 2; mi++)
#pragma unroll
                for (int ni = 0; ni < 8; ni++) {
                    mma_bf16(acc[mi][ni], ah[mi], bh[ni]);
                    mma_bf16(acc[mi][ni], ah[mi], bl[ni]);
                    mma_bf16(acc[mi][ni], al[mi], bh[ni]);
                }
        }
        if (t + 1 < nb) {
            cvt_sts((t + 1) & 1);   // other stage; WAR-safe via prev sync
            __syncthreads();
        }
    }

    // epilogue
#pragma unroll
    for (int mi = 0; mi < 2; mi++)
#pragma unroll
        for (int ni = 0; ni < 8; ni++) {
            int r0 = bm + wm + mi * 16 + g;
            int c0 = bn + wn + ni * 8 + tg;
#pragma unroll
            for (int half = 0; half < 2; half++) {
                int r = r0 + half * 8;
                float v0 = acc[mi][ni][half * 2 + 0] + bias[c0];
                float v1 = acc[mi][ni][half * 2 + 1] + bias[c0 + 1];
                if (EPI == EPI_PHI) {
                    v0 = (v0 > 0.f) ? (v0 + 1.f) : expf(v0);
                    v1 = (v1 > 0.f) ? (v1 + 1.f) : expf(v1);
                }
                if (EPI == EPI_GELU) {
                    v0 = 0.5f * v0 * (1.f + erff(v0 * 0.70710678118654752f));
                    v1 = 0.5f * v1 * (1.f + erff(v1 * 0.70710678118654752f));
                }
                if (EPI == EPI_RES) {
                    float2 rv = *(const float2*)(res + (size_t)r * N + c0);
                    v0 += rv.x; v1 += rv.y;
                }
                float2 o = make_float2(v0, v1);
                *(float2*)(Cmat + (size_t)r * N + c0) = o;
            }
        }
}

// ---------------- Pass A: per-chunk KV sums (e-split x2) -------------------
__global__ void chunk_kv_kernel() {
    __shared__ float ks[CCH * (HDIM + 1)];
    __shared__ float vs[CCH * (EHC + 1)];
    int blk = blockIdx.x;
    int eh = blk & 1;
    int hc = blk >> 1;
    int h = hc / NCH, c = hc % NCH, tid = threadIdx.x;
    int s0 = c * CCH;
    for (int i = tid; i < CCH * HDIM; i += 256) {
        int r = i >> 6, d = i & 63;
        ks[r * (HDIM + 1) + d] = g_k[(size_t)(s0 + r) * D_DIM + h * HDIM + d];
    }
    for (int i = tid; i < CCH * EHC; i += 256) {
        int r = i >> 5, e = i & 31;
        vs[r * (EHC + 1) + e] = g_v[(size_t)(s0 + r) * D_DIM + h * HDIM + eh * EHC + e];
    }
    __syncthreads();
    int d = tid >> 2, e0 = (tid & 3) * 8;
    float acc[8] = {};
    for (int s = 0; s < CCH; s++) {
        float kd = ks[s * (HDIM + 1) + d];
#pragma unroll
        for (int j = 0; j < 8; j++)
            acc[j] += kd * vs[s * (EHC + 1) + e0 + j];
    }
    float* outp = g_kv + ((size_t)(h * NCH + c) * HDIM + d) * HDIM + eh * EHC + e0;
#pragma unroll
    for (int j = 0; j < 8; j++) outp[j] = acc[j];
    if (eh == 0 && tid < HDIM) {
        float z = 0.f;
        for (int s = 0; s < CCH; s++) z += ks[s * (HDIM + 1) + tid];
        g_zc[(h * NCH + c) * HDIM + tid] = z;
    }
}

// ---------------- Pass B: exclusive prefix over chunks (float4) -----------
__global__ void prefix_kernel() {
    int idx = blockIdx.x * 256 + threadIdx.x;     // 16384 threads
    int h = idx >> 10, de4 = idx & 1023;
    const float4* in  = (const float4*)g_kv;
    float4*       out = (float4*)g_kvp;
    float4 run = make_float4(0.f, 0.f, 0.f, 0.f);
#pragma unroll 4
    for (int c = 0; c < NCH; c++) {
        size_t off = (size_t)(h * NCH + c) * 1024 + de4;
        float4 v = in[off];
        out[off] = run;
        run.x += v.x; run.y += v.y; run.z += v.z; run.w += v.w;
    }
    if (idx < H_NUM * HDIM) {
        int ho = idx / HDIM, dd = idx % HDIM;
        float rz = 0.f;
        for (int c = 0; c < NCH; c++) {
            int off = (ho * NCH + c) * HDIM + dd;
            float v = g_zc[off];
            g_zp[off] = rz;
            rz += v;
        }
    }
}

// ---------------- Pass C: per-chunk attention output (e-split x2) ---------
__global__ void chunk_attn_kernel() {
    extern __shared__ float sm[];
    float* qs = sm;                                  // CCH*(HDIM+1)
    float* kv = qs + CCH * (HDIM + 1);               // k full; v half in cols 0..31
    float* Ss = kv + CCH * (HDIM + 1);               // CCH*(CCH+1)
    float* kp = Ss + CCH * (CCH + 1);                // HDIM*(EHC+1)
    float* zp = kp + HDIM * (EHC + 1);               // HDIM
    float* dn = zp + HDIM;                           // CCH

    int blk = blockIdx.x;
    int eh = blk & 1;
    int hc = blk >> 1;
    int h = hc / NCH, c = hc % NCH, tid = threadIdx.x;
    int s0 = c * CCH;

    for (int i = tid; i < CCH * HDIM; i += 256) {
        int r = i >> 6, d = i & 63;
        qs[r * (HDIM + 1) + d] = g_q[(size_t)(s0 + r) * D_DIM + h * HDIM + d];
        kv[r * (HDIM + 1) + d] = g_k[(size_t)(s0 + r) * D_DIM + h * HDIM + d];
    }
    for (int i = tid; i < HDIM * EHC; i += 256) {
        int d = i >> 5, e = i & 31;
        kp[d * (EHC + 1) + e] =
            g_kvp[((size_t)(h * NCH + c) * HDIM + d) * HDIM + eh * EHC + e];
    }
    if (tid < HDIM) zp[tid] = g_zp[(h * NCH + c) * HDIM + tid];
    __syncthreads();

    {
        int t = tid >> 2, i0 = (tid & 3) * 16;
        for (int j = 0; j < 16; j++) {
            int i = i0 + j;
            float sc = 0.f;
            if (i <= t) {
#pragma unroll
                for (int d = 0; d < HDIM; d++)
                    sc += qs[t * (HDIM + 1) + d] * kv[i * (HDIM + 1) + d];
            }
            Ss[t * (CCH + 1) + i] = sc;
        }
    }
    __syncthreads();

    if (tid < CCH) {
        float dd = 1e-6f;
        for (int d = 0; d < HDIM; d++)
            dd += qs[tid * (HDIM + 1) + d] * zp[d];
        for (int i = 0; i < CCH; i++)
            dd += Ss[tid * (CCH + 1) + i];
        dn[tid] = dd;
    }
    for (int i = tid; i < CCH * EHC; i += 256) {
        int r = i >> 5, e = i & 31;
        kv[r * (HDIM + 1) + e] = g_v[(size_t)(s0 + r) * D_DIM + h * HDIM + eh * EHC + e];
    }
    __syncthreads();

    int t = tid >> 2, e0 = (tid & 3) * 8;
    float o[8] = {};
    for (int d = 0; d < HDIM; d++) {
        float qd = qs[t * (HDIM + 1) + d];
#pragma unroll
        for (int j = 0; j < 8; j++)
            o[j] += qd * kp[d * (EHC + 1) + e0 + j];
    }
    for (int i = 0; i < CCH; i++) {
        float sv = Ss[t * (CCH + 1) + i];
#pragma unroll
        for (int j = 0; j < 8; j++)
            o[j] += sv * kv[i * (HDIM + 1) + e0 + j];
    }
    float inv = 1.f / dn[t];
    float* op = g_attn + (size_t)(s0 + t) * D_DIM + h * HDIM + eh * EHC + e0;
#pragma unroll
    for (int j = 0; j < 8; j++) op[j] = o[j] * inv;
}

// ---------------- launch ---------------------------------------------------
extern "C" void kernel_launch(void* const* d_in, const int* in_sizes, int n_in,
                              void* d_out, int out_size) {
    const float* x   = (const float*)d_in[0];
    const float* Wq  = (const float*)d_in[1];  const float* bq  = (const float*)d_in[2];
    const float* Wk  = (const float*)d_in[3];  const float* bk  = (const float*)d_in[4];
    const float* Wv  = (const float*)d_in[5];  const float* bv  = (const float*)d_in[6];
    const float* Wo  = (const float*)d_in[7];  const float* bo  = (const float*)d_in[8];
    const float* W1  = (const float*)d_in[9];  const float* b1  = (const float*)d_in[10];
    const float* W2  = (const float*)d_in[11]; const float* b2  = (const float*)d_in[12];
    const float* g1  = (const float*)d_in[13]; const float* be1 = (const float*)d_in[14];
    const float* g2  = (const float*)d_in[15]; const float* be2 = (const float*)d_in[16];
    float* out = (float*)d_out;

    float *h, *q, *k, *v, *attn, *x2, *h2, *ff;
    cudaGetSymbolAddress((void**)&h,    g_h);
    cudaGetSymbolAddress((void**)&q,    g_q);
    cudaGetSymbolAddress((void**)&k,    g_k);
    cudaGetSymbolAddress((void**)&v,    g_v);
    cudaGetSymbolAddress((void**)&attn, g_attn);
    cudaGetSymbolAddress((void**)&x2,   g_x2);
    cudaGetSymbolAddress((void**)&h2,   g_h2);
    cudaGetSymbolAddress((void**)&ff,   g_ff);

    cudaFuncSetAttribute((const void*)gemm_mma<EPI_BIAS, MODE_ONE>,  cudaFuncAttributeMaxDynamicSharedMemorySize, SMEM_GEMM);
    cudaFuncSetAttribute((const void*)gemm_mma<EPI_PHI,  MODE_PAIR>, cudaFuncAttributeMaxDynamicSharedMemorySize, SMEM_GEMM);
    cudaFuncSetAttribute((const void*)gemm_mma<EPI_GELU, MODE_ONE>,  cudaFuncAttributeMaxDynamicSharedMemorySize, SMEM_GEMM);
    cudaFuncSetAttribute((const void*)gemm_mma<EPI_RES,  MODE_ONE>,  cudaFuncAttributeMaxDynamicSharedMemorySize, SMEM_GEMM);

    const int smem_attn = (2 * CCH * (HDIM + 1) + CCH * (CCH + 1) +
                           HDIM * (EHC + 1) + HDIM + CCH) * (int)sizeof(float);
    cudaFuncSetAttribute(chunk_attn_kernel,
                         cudaFuncAttributeMaxDynamicSharedMemorySize, smem_attn);

    dim3 gQK(D_DIM / 128, S_LEN / 128, 2);   // 256 CTAs
    dim3 gD (D_DIM / 128, S_LEN / 128);      // 128 CTAs
    dim3 gF (FF_DIM / 128, S_LEN / 128);     // 512 CTAs

    // LN1
    ln_kernel<<<S_LEN, 256>>>(x, g1, be1, h);
    // Q + K batched (phi epilogue), V separate
    gemm_mma<EPI_PHI, MODE_PAIR><<<gQK, 256, SMEM_GEMM>>>(
        h, Wq, Wk, bq, bk, nullptr, q, k, S_LEN, D_DIM, D_DIM);
    gemm_mma<EPI_BIAS, MODE_ONE><<<gD, 256, SMEM_GEMM>>>(
        h, Wv, nullptr, bv, nullptr, nullptr, v, nullptr, S_LEN, D_DIM, D_DIM);
    // chunked causal linear attention (e-split x2)
    chunk_kv_kernel  <<<H_NUM * NCH * 2, 256>>>();
    prefix_kernel    <<<H_NUM * HDIM * HDIM / 4 / 256, 256>>>();
    chunk_attn_kernel<<<H_NUM * NCH * 2, 256, smem_attn>>>();
    // O-proj + residual
    gemm_mma<EPI_RES, MODE_ONE><<<gD, 256, SMEM_GEMM>>>(
        attn, Wo, nullptr, bo, nullptr, x, x2, nullptr, S_LEN, D_DIM, D_DIM);
    // LN2
    ln_kernel<<<S_LEN, 256>>>(x2, g2, be2, h2);
    // FFN1 (GELU)
    gemm_mma<EPI_GELU, MODE_ONE><<<gF, 256, SMEM_GEMM>>>(
        h2, W1, nullptr, b1, nullptr, nullptr, ff, nullptr, S_LEN, FF_DIM, D_DIM);
    // FFN2 (+residual) -> out
    gemm_mma<EPI_RES, MODE_ONE><<<gD, 256, SMEM_GEMM>>>(
        ff, W2, nullptr, b2, nullptr, x2, out, nullptr, S_LEN, D_DIM, FF_DIM);
}

// round 17
// speedup vs baseline: 1.2731x; 1.2731x over previous
#include <cuda_runtime.h>
#include <cuda_bf16.h>
#include <math.h>
#include <stdint.h>

// Problem constants
#define S_LEN 2048
#define D_DIM 1024
#define H_NUM 16
#define HDIM  64
#define FF_DIM 4096
#define CCH   64
#define NCH   (S_LEN/CCH)
#define EHC   32                 // e-columns per split block

// ---------------- scratch (static device globals; no allocation) ----------
__device__ float g_h   [S_LEN*D_DIM];
__device__ float g_q   [S_LEN*D_DIM];
__device__ float g_k   [S_LEN*D_DIM];
__device__ float g_v   [S_LEN*D_DIM];
__device__ float g_attn[S_LEN*D_DIM];
__device__ float g_x2  [S_LEN*D_DIM];
__device__ float g_h2  [S_LEN*D_DIM];
__device__ float g_ff  [S_LEN*FF_DIM];
__device__ float g_kv  [H_NUM*NCH*HDIM*HDIM];
__device__ float g_kvp [H_NUM*NCH*HDIM*HDIM];
__device__ float g_zc  [H_NUM*NCH*HDIM];
__device__ float g_zp  [H_NUM*NCH*HDIM];

// ---------------- LayerNorm: one float4 per thread, single gmem read -------
__global__ void ln_kernel(const float* __restrict__ x,
                          const float* __restrict__ g,
                          const float* __restrict__ b,
                          float* __restrict__ out) {
    int row = blockIdx.x;
    int i4 = threadIdx.x * 4;
    const float* xr = x + (size_t)row * D_DIM;
    float4 xv = *(const float4*)(xr + i4);
    float s  = (xv.x + xv.y) + (xv.z + xv.w);
    float s2 = (xv.x * xv.x + xv.y * xv.y) + (xv.z * xv.z + xv.w * xv.w);
    __shared__ float sh[64];
    for (int off = 16; off > 0; off >>= 1) {
        s  += __shfl_down_sync(0xffffffffu, s,  off);
        s2 += __shfl_down_sync(0xffffffffu, s2, off);
    }
    int w = threadIdx.x >> 5, l = threadIdx.x & 31;
    if (l == 0) { sh[w] = s; sh[w + 32] = s2; }
    __syncthreads();
    if (threadIdx.x == 0) {
        float ts = 0.f, ts2 = 0.f;
        for (int i = 0; i < 8; i++) { ts += sh[i]; ts2 += sh[i + 32]; }
        float mu = ts / D_DIM;
        sh[0] = mu;
        sh[1] = rsqrtf(ts2 / D_DIM - mu * mu + 1e-5f);
    }
    __syncthreads();
    float mu = sh[0], rstd = sh[1];
    float4 gv = *(const float4*)(g + i4);
    float4 bv = *(const float4*)(b + i4);
    float4 o;
    o.x = (xv.x - mu) * rstd * gv.x + bv.x;
    o.y = (xv.y - mu) * rstd * gv.y + bv.y;
    o.z = (xv.z - mu) * rstd * gv.z + bv.z;
    o.w = (xv.w - mu) * rstd * gv.w + bv.w;
    *(float4*)(out + (size_t)row * D_DIM + i4) = o;
}

// ---------------- bf16-split tensor-core GEMM (NT) -------------------------
// C[M,N] = A[M,K] @ B[N,K]^T + epilogue, fp32 in/out.
// Each fp32 = hi_bf16 + lo_bf16; per k16: mma(hi,hi)+mma(hi,lo)+mma(lo,hi).
// 2-stage smem double buffer, one sync per K-tile (round-10/12 proven core).
enum { EPI_BIAS = 0, EPI_PHI = 1, EPI_GELU = 2, EPI_RES = 3 };
enum { MODE_ONE = 0, MODE_PAIR = 1 };

__device__ __forceinline__ void mma_bf16(float* c, const unsigned* a, const unsigned* b) {
    asm volatile(
        "mma.sync.aligned.m16n8k16.row.col.f32.bf16.bf16.f32 "
        "{%0,%1,%2,%3}, {%4,%5,%6,%7}, {%8,%9}, {%0,%1,%2,%3};\n"
        : "+f"(c[0]), "+f"(c[1]), "+f"(c[2]), "+f"(c[3])
        : "r"(a[0]), "r"(a[1]), "r"(a[2]), "r"(a[3]), "r"(b[0]), "r"(b[1]));
}

// fp32x4 -> packed hi (2x u32) + packed lo (2x u32); rn split.
__device__ __forceinline__ void cvt_pack(float4 v, uint2& hi, uint2& lo) {
    asm("cvt.rn.bf16x2.f32 %0, %1, %2;" : "=r"(hi.x) : "f"(v.y), "f"(v.x));
    asm("cvt.rn.bf16x2.f32 %0, %1, %2;" : "=r"(hi.y) : "f"(v.w), "f"(v.z));
    float hx = __uint_as_float(hi.x << 16);
    float hy = __uint_as_float(hi.x & 0xFFFF0000u);
    float hz = __uint_as_float(hi.y << 16);
    float hw = __uint_as_float(hi.y & 0xFFFF0000u);
    asm("cvt.rn.bf16x2.f32 %0, %1, %2;" : "=r"(lo.x) : "f"(v.y - hy), "f"(v.x - hx));
    asm("cvt.rn.bf16x2.f32 %0, %1, %2;" : "=r"(lo.y) : "f"(v.w - hw), "f"(v.z - hz));
}

#define LDSW 40
#define TILE_ELEMS (128 * LDSW)          // bf16 elems per tile
#define STAGE_ELEMS (4 * TILE_ELEMS)     // Ah,Al,Bh,Bl
#define SMEM_GEMM (2 * STAGE_ELEMS * 2)  // bytes = 81920

template <int EPI, int MODE>
__global__ __launch_bounds__(256, 1)
void gemm_mma(const float* __restrict__ A,
              const float* __restrict__ B0, const float* __restrict__ B1,
              const float* __restrict__ bias0, const float* __restrict__ bias1,
              const float* __restrict__ res,
              float* __restrict__ C0, float* __restrict__ C1,
              int M, int N, int K) {
    extern __shared__ __align__(16) __nv_bfloat16 SM[];

    const float* B    = B0;
    const float* bias = bias0;
    float*       Cmat = C0;
    if (MODE == MODE_PAIR && blockIdx.z == 1) { B = B1; bias = bias1; Cmat = C1; }

    const int tid  = threadIdx.x;
    const int bm   = blockIdx.y * 128, bn = blockIdx.x * 128;
    const int lane = tid & 31, warp = tid >> 5;
    const int wm   = (warp & 3) * 32;     // 4 warps along M
    const int wn   = (warp >> 2) * 64;    // 2 warps along N
    const int g    = lane >> 2;           // 0..7
    const int tg   = (lane & 3) * 2;      // 0,2,4,6

    const int lrow = tid >> 3;            // 0..31 (loader row)
    const int lcol = (tid & 7) * 4;       // 0..28 (float4 col)

    float acc[2][8][4];
#pragma unroll
    for (int i = 0; i < 2; i++)
#pragma unroll
        for (int j = 0; j < 8; j++)
#pragma unroll
            for (int e = 0; e < 4; e++) acc[i][j][e] = 0.f;

    const float* Ap = A + (size_t)(bm + lrow) * K + lcol;
    const float* Bp = B + (size_t)(bn + lrow) * K + lcol;

    float4 ar[4], br[4];
#pragma unroll
    for (int i = 0; i < 4; i++) {
        ar[i] = *(const float4*)(Ap + (size_t)(32 * i) * K);
        br[i] = *(const float4*)(Bp + (size_t)(32 * i) * K);
    }

    auto cvt_sts = [&](int s) {
        __nv_bfloat16* Ah = SM + s * STAGE_ELEMS;
        __nv_bfloat16* Al = Ah + TILE_ELEMS;
        __nv_bfloat16* Bh = Ah + 2 * TILE_ELEMS;
        __nv_bfloat16* Bl = Ah + 3 * TILE_ELEMS;
#pragma unroll
        for (int i = 0; i < 4; i++) {
            int r = lrow + 32 * i;
            uint2 hi, lo;
            cvt_pack(ar[i], hi, lo);
            *(uint2*)&Ah[r * LDSW + lcol] = hi;
            *(uint2*)&Al[r * LDSW + lcol] = lo;
            cvt_pack(br[i], hi, lo);
            *(uint2*)&Bh[r * LDSW + lcol] = hi;
            *(uint2*)&Bl[r * LDSW + lcol] = lo;
        }
    };

    cvt_sts(0);
    __syncthreads();

    const int nb = K / 32;
    for (int t = 0; t < nb; t++) {
        const int s = t & 1;
        if (t + 1 < nb) {
            int kt = (t + 1) * 32;
#pragma unroll
            for (int i = 0; i < 4; i++) {
                ar[i] = *(const float4*)(Ap + kt + (size_t)(32 * i) * K);
                br[i] = *(const float4*)(Bp + kt + (size_t)(32 * i) * K);
            }
        }
        const __nv_bfloat16* Ah = SM + s * STAGE_ELEMS;
        const __nv_bfloat16* Al = Ah + TILE_ELEMS;
        const __nv_bfloat16* Bh = Ah + 2 * TILE_ELEMS;
        const __nv_bfloat16* Bl = Ah + 3 * TILE_ELEMS;
#pragma unroll
        for (int kk = 0; kk < 32; kk += 16) {
            unsigned ah[2][4], al[2][4], bh[8][2], bl[8][2];
#pragma unroll
            for (int mi = 0; mi < 2; mi++) {
                int r0 = wm + mi * 16 + g;
                ah[mi][0] = *(const unsigned*)&Ah[(r0    ) * LDSW + kk + tg    ];
                ah[mi][1] = *(const unsigned*)&Ah[(r0 + 8) * LDSW + kk + tg    ];
                ah[mi][2] = *(const unsigned*)&Ah[(r0    ) * LDSW + kk + tg + 8];
                ah[mi][3] = *(const unsigned*)&Ah[(r0 + 8) * LDSW + kk + tg + 8];
                al[mi][0] = *(const unsigned*)&Al[(r0    ) * LDSW + kk + tg    ];
                al[mi][1] = *(const unsigned*)&Al[(r0 + 8) * LDSW + kk + tg    ];
                al[mi][2] = *(const unsigned*)&Al[(r0    ) * LDSW + kk + tg + 8];
                al[mi][3] = *(const unsigned*)&Al[(r0 + 8) * LDSW + kk + tg + 8];
            }
#pragma unroll
            for (int ni = 0; ni < 8; ni++) {
                int c0 = wn + ni * 8 + g;
                bh[ni][0] = *(const unsigned*)&Bh[c0 * LDSW + kk + tg    ];
                bh[ni][1] = *(const unsigned*)&Bh[c0 * LDSW + kk + tg + 8];
                bl[ni][0] = *(const unsigned*)&Bl[c0 * LDSW + kk + tg    ];
                bl[ni][1] = *(const unsigned*)&Bl[c0 * LDSW + kk + tg + 8];
            }
#pragma unroll
            for (int mi = 0; mi < 2; mi++)
#pragma unroll
                for (int ni = 0; ni < 8; ni++) {
                    mma_bf16(acc[mi][ni], ah[mi], bh[ni]);
                    mma_bf16(acc[mi][ni], ah[mi], bl[ni]);
                    mma_bf16(acc[mi][ni], al[mi], bh[ni]);
                }
        }
        if (t + 1 < nb) {
            cvt_sts((t + 1) & 1);   // other stage; WAR-safe via prev sync
            __syncthreads();
        }
    }

    // epilogue
#pragma unroll
    for (int mi = 0; mi < 2; mi++)
#pragma unroll
        for (int ni = 0; ni < 8; ni++) {
            int r0 = bm + wm + mi * 16 + g;
            int c0 = bn + wn + ni * 8 + tg;
#pragma unroll
            for (int half = 0; half < 2; half++) {
                int r = r0 + half * 8;
                float v0 = acc[mi][ni][half * 2 + 0] + bias[c0];
                float v1 = acc[mi][ni][half * 2 + 1] + bias[c0 + 1];
                if (EPI == EPI_PHI) {
                    v0 = (v0 > 0.f) ? (v0 + 1.f) : expf(v0);
                    v1 = (v1 > 0.f) ? (v1 + 1.f) : expf(v1);
                }
                if (EPI == EPI_GELU) {
                    v0 = 0.5f * v0 * (1.f + erff(v0 * 0.70710678118654752f));
                    v1 = 0.5f * v1 * (1.f + erff(v1 * 0.70710678118654752f));
                }
                if (EPI == EPI_RES) {
                    float2 rv = *(const float2*)(res + (size_t)r * N + c0);
                    v0 += rv.x; v1 += rv.y;
                }
                float2 o = make_float2(v0, v1);
                *(float2*)(Cmat + (size_t)r * N + c0) = o;
            }
        }
}

// ---------------- Pass A: per-chunk KV sums (e-split x2) -------------------
__global__ void chunk_kv_kernel() {
    __shared__ float ks[CCH * (HDIM + 1)];
    __shared__ float vs[CCH * (EHC + 1)];
    int blk = blockIdx.x;
    int eh = blk & 1;
    int hc = blk >> 1;
    int h = hc / NCH, c = hc % NCH, tid = threadIdx.x;
    int s0 = c * CCH;
    for (int i = tid; i < CCH * HDIM; i += 256) {
        int r = i >> 6, d = i & 63;
        ks[r * (HDIM + 1) + d] = g_k[(size_t)(s0 + r) * D_DIM + h * HDIM + d];
    }
    for (int i = tid; i < CCH * EHC; i += 256) {
        int r = i >> 5, e = i & 31;
        vs[r * (EHC + 1) + e] = g_v[(size_t)(s0 + r) * D_DIM + h * HDIM + eh * EHC + e];
    }
    __syncthreads();
    int d = tid >> 2, e0 = (tid & 3) * 8;
    float acc[8] = {};
    for (int s = 0; s < CCH; s++) {
        float kd = ks[s * (HDIM + 1) + d];
#pragma unroll
        for (int j = 0; j < 8; j++)
            acc[j] += kd * vs[s * (EHC + 1) + e0 + j];
    }
    float* outp = g_kv + ((size_t)(h * NCH + c) * HDIM + d) * HDIM + eh * EHC + e0;
#pragma unroll
    for (int j = 0; j < 8; j++) outp[j] = acc[j];
    if (eh == 0 && tid < HDIM) {
        float z = 0.f;
        for (int s = 0; s < CCH; s++) z += ks[s * (HDIM + 1) + tid];
        g_zc[(h * NCH + c) * HDIM + tid] = z;
    }
}

// ---------------- Pass B: exclusive prefix over chunks (float4) -----------
__global__ void prefix_kernel() {
    int idx = blockIdx.x * 256 + threadIdx.x;     // 16384 threads
    int h = idx >> 10, de4 = idx & 1023;
    const float4* in  = (const float4*)g_kv;
    float4*       out = (float4*)g_kvp;
    float4 run = make_float4(0.f, 0.f, 0.f, 0.f);
#pragma unroll 4
    for (int c = 0; c < NCH; c++) {
        size_t off = (size_t)(h * NCH + c) * 1024 + de4;
        float4 v = in[off];
        out[off] = run;
        run.x += v.x; run.y += v.y; run.z += v.z; run.w += v.w;
    }
    if (idx < H_NUM * HDIM) {
        int ho = idx / HDIM, dd = idx % HDIM;
        float rz = 0.f;
        for (int c = 0; c < NCH; c++) {
            int off = (ho * NCH + c) * HDIM + dd;
            float v = g_zc[off];
            g_zp[off] = rz;
            rz += v;
        }
    }
}

// ---------------- Pass C: per-chunk attention output (e-split x2) ---------
__global__ void chunk_attn_kernel() {
    extern __shared__ float sm[];
    float* qs = sm;                                  // CCH*(HDIM+1)
    float* kv = qs + CCH * (HDIM + 1);               // k full; v half in cols 0..31
    float* Ss = kv + CCH * (HDIM + 1);               // CCH*(CCH+1)
    float* kp = Ss + CCH * (CCH + 1);                // HDIM*(EHC+1)
    float* zp = kp + HDIM * (EHC + 1);               // HDIM
    float* dn = zp + HDIM;                           // CCH

    int blk = blockIdx.x;
    int eh = blk & 1;
    int hc = blk >> 1;
    int h = hc / NCH, c = hc % NCH, tid = threadIdx.x;
    int s0 = c * CCH;

    for (int i = tid; i < CCH * HDIM; i += 256) {
        int r = i >> 6, d = i & 63;
        qs[r * (HDIM + 1) + d] = g_q[(size_t)(s0 + r) * D_DIM + h * HDIM + d];
        kv[r * (HDIM + 1) + d] = g_k[(size_t)(s0 + r) * D_DIM + h * HDIM + d];
    }
    for (int i = tid; i < HDIM * EHC; i += 256) {
        int d = i >> 5, e = i & 31;
        kp[d * (EHC + 1) + e] =
            g_kvp[((size_t)(h * NCH + c) * HDIM + d) * HDIM + eh * EHC + e];
    }
    if (tid < HDIM) zp[tid] = g_zp[(h * NCH + c) * HDIM + tid];
    __syncthreads();

    {
        int t = tid >> 2, i0 = (tid & 3) * 16;
        for (int j = 0; j < 16; j++) {
            int i = i0 + j;
            float sc = 0.f;
            if (i <= t) {
#pragma unroll
                for (int d = 0; d < HDIM; d++)
                    sc += qs[t * (HDIM + 1) + d] * kv[i * (HDIM + 1) + d];
            }
            Ss[t * (CCH + 1) + i] = sc;
        }
    }
    __syncthreads();

    if (tid < CCH) {
        float dd = 1e-6f;
        for (int d = 0; d < HDIM; d++)
            dd += qs[tid * (HDIM + 1) + d] * zp[d];
        for (int i = 0; i < CCH; i++)
            dd += Ss[tid * (CCH + 1) + i];
        dn[tid] = dd;
    }
    for (int i = tid; i < CCH * EHC; i += 256) {
        int r = i >> 5, e = i & 31;
        kv[r * (HDIM + 1) + e] = g_v[(size_t)(s0 + r) * D_DIM + h * HDIM + eh * EHC + e];
    }
    __syncthreads();

    int t = tid >> 2, e0 = (tid & 3) * 8;
    float o[8] = {};
    for (int d = 0; d < HDIM; d++) {
        float qd = qs[t * (HDIM + 1) + d];
#pragma unroll
        for (int j = 0; j < 8; j++)
            o[j] += qd * kp[d * (EHC + 1) + e0 + j];
    }
    for (int i = 0; i < CCH; i++) {
        float sv = Ss[t * (CCH + 1) + i];
#pragma unroll
        for (int j = 0; j < 8; j++)
            o[j] += sv * kv[i * (HDIM + 1) + e0 + j];
    }
    float inv = 1.f / dn[t];
    float* op = g_attn + (size_t)(s0 + t) * D_DIM + h * HDIM + eh * EHC + e0;
#pragma unroll
    for (int j = 0; j < 8; j++) op[j] = o[j] * inv;
}

// ---------------- launch ---------------------------------------------------
extern "C" void kernel_launch(void* const* d_in, const int* in_sizes, int n_in,
                              void* d_out, int out_size) {
    const float* x   = (const float*)d_in[0];
    const float* Wq  = (const float*)d_in[1];  const float* bq  = (const float*)d_in[2];
    const float* Wk  = (const float*)d_in[3];  const float* bk  = (const float*)d_in[4];
    const float* Wv  = (const float*)d_in[5];  const float* bv  = (const float*)d_in[6];
    const float* Wo  = (const float*)d_in[7];  const float* bo  = (const float*)d_in[8];
    const float* W1  = (const float*)d_in[9];  const float* b1  = (const float*)d_in[10];
    const float* W2  = (const float*)d_in[11]; const float* b2  = (const float*)d_in[12];
    const float* g1  = (const float*)d_in[13]; const float* be1 = (const float*)d_in[14];
    const float* g2  = (const float*)d_in[15]; const float* be2 = (const float*)d_in[16];
    float* out = (float*)d_out;

    float *h, *q, *k, *v, *attn, *x2, *h2, *ff;
    cudaGetSymbolAddress((void**)&h,    g_h);
    cudaGetSymbolAddress((void**)&q,    g_q);
    cudaGetSymbolAddress((void**)&k,    g_k);
    cudaGetSymbolAddress((void**)&v,    g_v);
    cudaGetSymbolAddress((void**)&attn, g_attn);
    cudaGetSymbolAddress((void**)&x2,   g_x2);
    cudaGetSymbolAddress((void**)&h2,   g_h2);
    cudaGetSymbolAddress((void**)&ff,   g_ff);

    cudaFuncSetAttribute((const void*)gemm_mma<EPI_BIAS, MODE_ONE>,  cudaFuncAttributeMaxDynamicSharedMemorySize, SMEM_GEMM);
    cudaFuncSetAttribute((const void*)gemm_mma<EPI_PHI,  MODE_PAIR>, cudaFuncAttributeMaxDynamicSharedMemorySize, SMEM_GEMM);
    cudaFuncSetAttribute((const void*)gemm_mma<EPI_GELU, MODE_ONE>,  cudaFuncAttributeMaxDynamicSharedMemorySize, SMEM_GEMM);
    cudaFuncSetAttribute((const void*)gemm_mma<EPI_RES,  MODE_ONE>,  cudaFuncAttributeMaxDynamicSharedMemorySize, SMEM_GEMM);

    const int smem_attn = (2 * CCH * (HDIM + 1) + CCH * (CCH + 1) +
                           HDIM * (EHC + 1) + HDIM + CCH) * (int)sizeof(float);
    cudaFuncSetAttribute(chunk_attn_kernel,
                         cudaFuncAttributeMaxDynamicSharedMemorySize, smem_attn);

    dim3 gQK(D_DIM / 128, S_LEN / 128, 2);   // 256 CTAs
    dim3 gD (D_DIM / 128, S_LEN / 128);      // 128 CTAs
    dim3 gF (FF_DIM / 128, S_LEN / 128);     // 512 CTAs

    // LN1
    ln_kernel<<<S_LEN, 256>>>(x, g1, be1, h);
    // Q + K batched (phi epilogue), V separate
    gemm_mma<EPI_PHI, MODE_PAIR><<<gQK, 256, SMEM_GEMM>>>(
        h, Wq, Wk, bq, bk, nullptr, q, k, S_LEN, D_DIM, D_DIM);
    gemm_mma<EPI_BIAS, MODE_ONE><<<gD, 256, SMEM_GEMM>>>(
        h, Wv, nullptr, bv, nullptr, nullptr, v, nullptr, S_LEN, D_DIM, D_DIM);
    // chunked causal linear attention (e-split x2)
    chunk_kv_kernel  <<<H_NUM * NCH * 2, 256>>>();
    prefix_kernel    <<<H_NUM * HDIM * HDIM / 4 / 256, 256>>>();
    chunk_attn_kernel<<<H_NUM * NCH * 2, 256, smem_attn>>>();
    // O-proj + residual
    gemm_mma<EPI_RES, MODE_ONE><<<gD, 256, SMEM_GEMM>>>(
        attn, Wo, nullptr, bo, nullptr, x, x2, nullptr, S_LEN, D_DIM, D_DIM);
    // LN2
    ln_kernel<<<S_LEN, 256>>>(x2, g2, be2, h2);
    // FFN1 (GELU)
    gemm_mma<EPI_GELU, MODE_ONE><<<gF, 256, SMEM_GEMM>>>(
        h2, W1, nullptr, b1, nullptr, nullptr, ff, nullptr, S_LEN, FF_DIM, D_DIM);
    // FFN2 (+residual) -> out
    gemm_mma<EPI_RES, MODE_ONE><<<gD, 256, SMEM_GEMM>>>(
        ff, W2, nullptr, b2, nullptr, x2, out, nullptr, S_LEN, D_DIM, FF_DIM);
}